// round 3
// baseline (speedup 1.0000x reference)
#include <cuda_runtime.h>
#include <math.h>

// Problem constants (fixed by the reference)
#define N_BAGS   64
#define GRID_W   96
#define NCELLS   (N_BAGS * GRID_W * GRID_W)   // 589824
#define CAP      16                            // bucket capacity; Poisson(0.222) => overflow ~impossible
#define NQ       512
#define NMEM     131072
#define DIM      256

// Scratch: device globals (no runtime allocation allowed).
__device__ int g_cell_count[NCELLS];
__device__ int g_cell_items[NCELLS * CAP];

// ---------------------------------------------------------------------------
// Pass 1: scatter memory-row indices into (bag, y, x) cells.
// ---------------------------------------------------------------------------
__global__ void count_kernel(const int* __restrict__ bag_idxs,
                             const int* __restrict__ xs,
                             const int* __restrict__ ys) {
    int n = blockIdx.x * blockDim.x + threadIdx.x;
    if (n >= NMEM) return;
    int cell = (bag_idxs[n] * GRID_W + ys[n]) * GRID_W + xs[n];
    int slot = atomicAdd(&g_cell_count[cell], 1);
    if (slot < CAP) g_cell_items[cell * CAP + slot] = n;
}

// ---------------------------------------------------------------------------
// Pass 2: one warp per query. Probe the 8 neighbor cells (these are exactly
// the rows with 0 < d2 < 4), compute exact fp32 dot products against the
// (few) candidates, accumulate exp(dot / (||q|| * 0.2)).
// ---------------------------------------------------------------------------
__global__ void query_kernel(const float* __restrict__ q,
                             const float* __restrict__ memory,
                             const int* __restrict__ bag_idx,
                             const int* __restrict__ xc,
                             const int* __restrict__ yc,
                             float* __restrict__ out) {
    int warp = (blockIdx.x * blockDim.x + threadIdx.x) >> 5;
    int lane = threadIdx.x & 31;
    if (warp >= NQ) return;

    // Each lane holds 8 consecutive elements of the query row (2 x float4).
    const float* qrow = q + warp * DIM + lane * 8;
    float4 a = *(const float4*)(qrow);
    float4 b = *(const float4*)(qrow + 4);

    // ||q||^2 via warp reduce
    float ss = a.x * a.x + a.y * a.y + a.z * a.z + a.w * a.w
             + b.x * b.x + b.y * b.y + b.z * b.z + b.w * b.w;
    #pragma unroll
    for (int o = 16; o; o >>= 1) ss += __shfl_xor_sync(0xFFFFFFFFu, ss, o);
    // 1 / (||q|| * TEMP)  with TEMP = 0.2  ->  5 / ||q||
    float inv = rsqrtf(ss) * 5.0f;

    int bag = bag_idx[warp];
    int x0  = xc[warp];
    int y0  = yc[warp];

    float s = 0.0f;
    #pragma unroll
    for (int dy = -1; dy <= 1; dy++) {
        #pragma unroll
        for (int dx = -1; dx <= 1; dx++) {
            if (dx == 0 && dy == 0) continue;           // d2 == 0 excluded
            int x = x0 + dx, y = y0 + dy;
            if (x < 0 || x >= GRID_W || y < 0 || y >= GRID_W) continue;
            int cell = (bag * GRID_W + y) * GRID_W + x;
            int cnt = g_cell_count[cell];
            if (cnt > CAP) cnt = CAP;
            for (int i = 0; i < cnt; i++) {
                int n = g_cell_items[cell * CAP + i];
                const float* mr = memory + (size_t)n * DIM + lane * 8;
                float4 m0 = *(const float4*)(mr);
                float4 m1 = *(const float4*)(mr + 4);
                float d = a.x * m0.x + a.y * m0.y + a.z * m0.z + a.w * m0.w
                        + b.x * m1.x + b.y * m1.y + b.z * m1.z + b.w * m1.w;
                #pragma unroll
                for (int o = 16; o; o >>= 1) d += __shfl_xor_sync(0xFFFFFFFFu, d, o);
                s += expf(d * inv);
            }
        }
    }
    if (lane == 0) out[warp] = s;
}

extern "C" void kernel_launch(void* const* d_in, const int* in_sizes, int n_in,
                              void* d_out, int out_size) {
    const float* q       = (const float*)d_in[0];   // [512, 256]
    const float* memory  = (const float*)d_in[1];   // [131072, 256]
    const int*   bag_idx = (const int*)d_in[2];     // [512]
    const int*   x_coord = (const int*)d_in[3];     // [512]
    const int*   y_coord = (const int*)d_in[4];     // [512]
    const int*   bag_idxs = (const int*)d_in[5];    // [131072]
    const int*   x_coords = (const int*)d_in[6];    // [131072]
    const int*   y_coords = (const int*)d_in[7];    // [131072]
    float* out = (float*)d_out;                     // [512]

    // Zero the cell counters (graph-capturable async memset, no allocation).
    void* count_ptr = nullptr;
    cudaGetSymbolAddress(&count_ptr, g_cell_count);
    cudaMemsetAsync(count_ptr, 0, NCELLS * sizeof(int));

    // Pass 1: bucket memory rows by (bag, y, x).
    count_kernel<<<(NMEM + 255) / 256, 256>>>(bag_idxs, x_coords, y_coords);

    // Pass 2: one warp per query; 512 warps total.
    const int threads = 128;                        // 4 warps / block
    const int blocks  = (NQ * 32 + threads - 1) / threads;  // 128 blocks
    query_kernel<<<blocks, threads>>>(q, memory, bag_idx, x_coord, y_coord, out);
}